// round 3
// baseline (speedup 1.0000x reference)
#include <cuda_runtime.h>

#define HW 16384
#define OFF_PI 0
#define OFF_MU 2097152
#define OFF_SIG 35651584
#define OFF_G 37748736

#define BSTRIDE 132

// shared layout (float offsets)
#define SH_A 0         // 152*128 = 19456 : A tile [c][pix]  (x | mu | rho)
#define SH_B 19456     // 152*132 = 20064 : Wmu^T [c][o] padded stride
#define SH_S 39520     // 152*8 = 1216    : Wsig^T [c][j]
#define SH_BMU 40736   // 128
#define SH_WPI 40864   // 128
#define SH_MISC 40992  // 32 : bpi[0..7] bsig[8..15] Wg[16..23] bg[24]
#define SH_AL 41024    // 8*128 : alpha [k][pix]
#define SH_PIV 42048   // 8*128 : pi    [k][pix]
#define SH_PIN 43072   // 8*128 : pi_new[j][pix]
#define SH_SIG 44096   // 8*128 : sigma-matvec mu_new partial [j][pix]
#define SH_D2 45120    // 8*128 : dist2 partial [k][pix]
#define SH_TOT 46144
#define SMEM_BYTES (SH_TOT * 4)

__device__ __forceinline__ unsigned long long pack2(float a, float b) {
    unsigned long long r;
    asm("mov.b64 %0, {%1,%2};" : "=l"(r) : "f"(a), "f"(b));
    return r;
}
__device__ __forceinline__ unsigned long long ffma2(unsigned long long a,
                                                    unsigned long long b,
                                                    unsigned long long c) {
    unsigned long long d;
    asm("fma.rn.f32x2 %0, %1, %2, %3;" : "=l"(d) : "l"(a), "l"(b), "l"(c));
    return d;
}
__device__ __forceinline__ float2 unpack2(unsigned long long v) {
    float2 f;
    asm("mov.b64 {%0,%1}, %2;" : "=f"(f.x), "=f"(f.y) : "l"(v));
    return f;
}

extern "C" __global__ void __launch_bounds__(256, 1)
gmm_block_kernel(const float* __restrict__ x, const float* __restrict__ pi_in,
                 const float* __restrict__ mu, const float* __restrict__ sigma,
                 const float* __restrict__ Wpi, const float* __restrict__ bpi,
                 const float* __restrict__ Wmu, const float* __restrict__ bmu,
                 const float* __restrict__ Wsig, const float* __restrict__ bsig,
                 const float* __restrict__ Wg, const float* __restrict__ bg,
                 float* __restrict__ out) {
    extern __shared__ float sh[];
    const int tid = threadIdx.x;
    const int blk = blockIdx.x;          // 2048 CTAs, 128 pixels each
    const int b = blk >> 7;
    const int hw0 = (blk & 127) << 7;

    // ---------------- stage 1: weights, x tile, zero reduction buffers ------
    for (int i = tid; i < 2048; i += 256) {
        int c = i >> 7, p = i & 127;
        sh[SH_A + c * 128 + p] = x[(b * 16 + c) * HW + hw0 + p];
    }
    for (int i = tid; i < 19456; i += 256) {   // Wmu[o][c] -> shB[c][o]
        int o = i / 152, c = i - o * 152;
        sh[SH_B + c * BSTRIDE + o] = Wmu[i];
    }
    for (int i = tid; i < 1216; i += 256) {    // Wsig[j][c] -> shS[c][j]
        int j = i / 152, c = i - j * 152;
        sh[SH_S + c * 8 + j] = Wsig[i];
    }
    if (tid < 128) {
        sh[SH_BMU + tid] = bmu[tid];
        sh[SH_WPI + tid] = Wpi[tid];
    } else if (tid < 136) {
        int k = tid - 128;
        sh[SH_MISC + k] = bpi[k];
        sh[SH_MISC + 8 + k] = bsig[k];
        sh[SH_MISC + 16 + k] = Wg[k];
    }
    if (tid == 255) sh[SH_MISC + 24] = bg[0];
    for (int i = tid; i < 1024; i += 256) {
        sh[SH_SIG + i] = 0.f;
        sh[SH_D2 + i] = 0.f;
    }
    __syncthreads();

    // ---------------- stage 2: stream mu once, fuse dens/alpha/rho ---------
    {
        const int p = tid & 127, half = tid >> 7;
        const float* mup = mu + (b * 128) * HW + hw0 + p;
#pragma unroll
        for (int kg = 0; kg < 4; kg++) {
            int k = half * 4 + kg;
            float dk = 0.f;
#pragma unroll
            for (int c = 0; c < 16; c++) {
                int ch = k * 16 + c;
                float v = mup[ch * HW];
                sh[SH_A + (16 + ch) * 128 + p] = v;
                float d = sh[SH_A + c * 128 + p] - v;
                dk = fmaf(d, d, dk);
            }
            float sg = sigma[(b * 8 + k) * HW + hw0 + p];
            float pv = pi_in[(b * 8 + k) * HW + hw0 + p];
            float s2 = sg * sg;
            float t = 6.283185307179586f * s2;
            float t2 = t * t, t4 = t2 * t2;
            float dens = __expf(-dk / (2.f * s2)) / (t4 * t4);
            float a = pv * dens;
            sh[SH_AL + k * 128 + p] = a;
            sh[SH_PIV + k * 128 + p] = pv;
            sh[SH_A + (144 + k) * 128 + p] = a * dens;  // rho
        }
    }
    __syncthreads();

    // ---------------- stage 3: pi_new (softmax) on 128 threads -------------
    if (tid < 128) {
        const int p = tid;
        float piv[8], al[8], z[8];
#pragma unroll
        for (int k = 0; k < 8; k++) {
            piv[k] = sh[SH_PIV + k * 128 + p];
            al[k] = sh[SH_AL + k * 128 + p];
        }
        float zmax = -1e30f;
#pragma unroll
        for (int j = 0; j < 8; j++) {
            float zj = sh[SH_MISC + j];
#pragma unroll
            for (int i = 0; i < 8; i++) {
                zj = fmaf(sh[SH_WPI + j * 16 + i], piv[i], zj);
                zj = fmaf(sh[SH_WPI + j * 16 + 8 + i], al[i], zj);
            }
            z[j] = zj;
            zmax = fmaxf(zmax, zj);
        }
        float s = 0.f;
#pragma unroll
        for (int j = 0; j < 8; j++) {
            z[j] = __expf(z[j] - zmax);
            s += z[j];
        }
        float inv = 1.0f / s;
#pragma unroll
        for (int j = 0; j < 8; j++) {
            float pn = z[j] * inv;
            sh[SH_PIN + j * 128 + p] = pn;
            out[OFF_PI + (b * 8 + j) * HW + hw0 + p] = pn;
        }
    }

    // ---------------- stage 4: tiled GEMM, 8x8 microtile per thread --------
    const int tm = tid & 15;   // pixel octet
    const int tn = tid >> 4;   // output octet
    const float* Abase = sh + SH_A + tm * 8;
    const float* Bbase = sh + SH_B + tn * 8;

    unsigned long long acc[32];
    {
        float4 m0 = *(const float4*)(sh + SH_BMU + tn * 8);
        float4 m1 = *(const float4*)(sh + SH_BMU + tn * 8 + 4);
        float bb[8] = {m0.x, m0.y, m0.z, m0.w, m1.x, m1.y, m1.z, m1.w};
#pragma unroll
        for (int o = 0; o < 8; o++)
#pragma unroll
            for (int pp = 0; pp < 4; pp++) acc[o * 4 + pp] = pack2(bb[o], bb[o]);
    }

#pragma unroll 1
    for (int c = 0; c < 152; c += 4) {
#pragma unroll
        for (int u = 0; u < 4; u++) {
            const float* ap = Abase + (c + u) * 128;
            const float* bp = Bbase + (c + u) * BSTRIDE;
            ulonglong2 a01 = *(const ulonglong2*)ap;
            ulonglong2 a23 = *(const ulonglong2*)(ap + 4);
            float4 b0 = *(const float4*)bp;
            float4 b1 = *(const float4*)(bp + 4);
            unsigned long long ad[4] = {a01.x, a01.y, a23.x, a23.y};
            float bs[8] = {b0.x, b0.y, b0.z, b0.w, b1.x, b1.y, b1.z, b1.w};
#pragma unroll
            for (int o = 0; o < 8; o++) {
                unsigned long long bbp = pack2(bs[o], bs[o]);
#pragma unroll
                for (int pp = 0; pp < 4; pp++)
                    acc[o * 4 + pp] = ffma2(ad[pp], bbp, acc[o * 4 + pp]);
            }
        }
    }

    // ---------------- stage 5: relu + store mu_new + partial reductions ----
    // relu in place
#pragma unroll
    for (int i = 0; i < 32; i++) {
        float2 f = unpack2(acc[i]);
        acc[i] = pack2(fmaxf(f.x, 0.f), fmaxf(f.y, 0.f));
    }
    // store mu_new (o-major, 2x float4 per output row)
    {
        float* outMu = out + OFF_MU + (b * 128 + tn * 8) * HW + hw0 + tm * 8;
#pragma unroll
        for (int o = 0; o < 8; o++) {
            float2 q0 = unpack2(acc[o * 4 + 0]);
            float2 q1 = unpack2(acc[o * 4 + 1]);
            float2 q2 = unpack2(acc[o * 4 + 2]);
            float2 q3 = unpack2(acc[o * 4 + 3]);
            float4 s0 = make_float4(q0.x, q0.y, q1.x, q1.y);
            float4 s1 = make_float4(q2.x, q2.y, q3.x, q3.y);
            *(float4*)(outMu + o * HW) = s0;
            *(float4*)(outMu + o * HW + 4) = s1;
        }
    }
    // sigma matvec partials (mu_new part) + dist2 partials
    {
        const int kk = tn >> 1;            // all 8 outputs share one k group
        const int cbase = (tn & 1) * 8;    // x channel base within group
        const unsigned long long neg1 = pack2(-1.f, -1.f);
#pragma unroll
        for (int pp = 0; pp < 4; pp++) {
            int pix = tm * 8 + 2 * pp;
            // sigma partials, packed over the pixel pair
#pragma unroll
            for (int j = 0; j < 8; j++) {
                unsigned long long sp = pack2(0.f, 0.f);
#pragma unroll
                for (int o = 0; o < 8; o++) {
                    float w = sh[SH_S + (16 + tn * 8 + o) * 8 + j];
                    sp = ffma2(acc[o * 4 + pp], pack2(w, w), sp);
                }
                float2 f = unpack2(sp);
                atomicAdd(&sh[SH_SIG + j * 128 + pix], f.x);
                atomicAdd(&sh[SH_SIG + j * 128 + pix + 1], f.y);
            }
            // dist2 partial: sum over this thread's 8 outputs of (x - mu_new)^2
            unsigned long long dacc = pack2(0.f, 0.f);
#pragma unroll
            for (int o = 0; o < 8; o++) {
                int cx = cbase + o;
                unsigned long long xv =
                    *(const unsigned long long*)(sh + SH_A + cx * 128 + pix);
                unsigned long long diff = ffma2(acc[o * 4 + pp], neg1, xv);
                dacc = ffma2(diff, diff, dacc);
            }
            float2 f = unpack2(dacc);
            atomicAdd(&sh[SH_D2 + kk * 128 + pix], f.x);
            atomicAdd(&sh[SH_D2 + kk * 128 + pix + 1], f.y);
        }
    }
    __syncthreads();

    // ---------------- stage 6: per-pixel finalize (sigma_new, dens2, gamma)
    if (tid < 128) {
        const int p = tid;
        float g = sh[SH_MISC + 24];  // bg
#pragma unroll
        for (int j = 0; j < 8; j++) {
            float s = sh[SH_MISC + 8 + j] + sh[SH_SIG + j * 128 + p];
#pragma unroll
            for (int c = 0; c < 16; c++)
                s = fmaf(sh[SH_S + c * 8 + j], sh[SH_A + c * 128 + p], s);
#pragma unroll
            for (int r = 0; r < 8; r++)
                s = fmaf(sh[SH_S + (144 + r) * 8 + j],
                         sh[SH_A + (144 + r) * 128 + p], s);
            float sn = __expf(fmaxf(s, 0.f));
            out[OFF_SIG + (b * 8 + j) * HW + hw0 + p] = sn;
            // dens2 (component j == k index here)
            float s2 = sn * sn;
            float t = 6.283185307179586f * s2;
            float t2 = t * t, t4 = t2 * t2;
            float dens2 =
                __expf(-sh[SH_D2 + j * 128 + p] / (2.f * s2)) / (t4 * t4);
            g = fmaf(sh[SH_MISC + 16 + j], sh[SH_PIN + j * 128 + p] * dens2, g);
        }
        out[OFF_G + b * HW + hw0 + p] = 1.0f / (1.0f + __expf(-g));
    }
}

extern "C" void kernel_launch(void* const* d_in, const int* in_sizes, int n_in,
                              void* d_out, int out_size) {
    (void)in_sizes;
    (void)n_in;
    (void)out_size;
    const float* x = (const float*)d_in[0];
    const float* pi = (const float*)d_in[1];
    const float* mu = (const float*)d_in[2];
    const float* sigma = (const float*)d_in[3];
    const float* Wpi = (const float*)d_in[4];
    const float* bpi = (const float*)d_in[5];
    const float* Wmu = (const float*)d_in[6];
    const float* bmu = (const float*)d_in[7];
    const float* Wsig = (const float*)d_in[8];
    const float* bsig = (const float*)d_in[9];
    const float* Wg = (const float*)d_in[10];
    const float* bg = (const float*)d_in[11];
    float* out = (float*)d_out;

    cudaFuncSetAttribute(gmm_block_kernel,
                         cudaFuncAttributeMaxDynamicSharedMemorySize,
                         SMEM_BYTES);
    gmm_block_kernel<<<2048, 256, SMEM_BYTES>>>(x, pi, mu, sigma, Wpi, bpi, Wmu,
                                                bmu, Wsig, bsig, Wg, bg, out);
}